// round 7
// baseline (speedup 1.0000x reference)
#include <cuda_runtime.h>
#include <cuda_bf16.h>
#include <cuda_fp16.h>
#include <cstdint>
#include <math.h>

#define S_LEN 2048
#define HID   2048
#define NH    32
#define NKV   4
#define HD    128
#define NQ    (NH * HD)    // 4096
#define NKVD  (NKV * HD)   // 512
#define NQKV  (NQ + 2 * NKVD)  // 5120

// ---------------------------------------------------------------------------
// Scratch (device globals — no allocation allowed)
// ---------------------------------------------------------------------------
__device__ float g_qkv[S_LEN * NQKV];

__device__ __nv_bfloat16 g_xh[S_LEN * HID];
__device__ __nv_bfloat16 g_xl[S_LEN * HID];
__device__ __nv_bfloat16 g_wqkvTh[NQKV * HID];
__device__ __nv_bfloat16 g_wqkvTl[NQKV * HID];
__device__ __nv_bfloat16 g_woTh[HID * NQ];
__device__ __nv_bfloat16 g_woTl[HID * NQ];
__device__ __nv_bfloat16 g_ath[S_LEN * NQ];
__device__ __nv_bfloat16 g_atl[S_LEN * NQ];

__device__ __half g_q16h[S_LEN * NQ];
__device__ __half g_q16l[S_LEN * NQ];
__device__ __half g_k16h[S_LEN * NKVD];
__device__ __half g_k16l[S_LEN * NKVD];
__device__ __half g_v16[S_LEN * NKVD];

// ---------------------------------------------------------------------------
// helpers
// ---------------------------------------------------------------------------
__device__ __forceinline__ uint32_t smem_u32(const void* p) {
    uint32_t a;
    asm("{ .reg .u64 t; cvta.to.shared.u64 t, %1; cvt.u32.u64 %0, t; }"
        : "=r"(a) : "l"(p));
    return a;
}

__device__ __forceinline__ void cpa16(uint32_t dst, const void* src) {
    asm volatile(
        "{\n\t.reg .u64 g;\n\tcvta.to.global.u64 g, %1;\n\t"
        "cp.async.cg.shared.global [%0], [g], 16;\n\t}"
        :: "r"(dst), "l"(src) : "memory");
}
#define CPA_COMMIT() asm volatile("cp.async.commit_group;" ::: "memory")
#define CPA_WAIT1()  asm volatile("cp.async.wait_group 1;" ::: "memory")
#define CPA_WAIT0()  asm volatile("cp.async.wait_group 0;" ::: "memory")

#define LDSM4(r, addr) \
    asm volatile("ldmatrix.sync.aligned.m8n8.x4.shared.b16 {%0,%1,%2,%3}, [%4];" \
        : "=r"((r)[0]), "=r"((r)[1]), "=r"((r)[2]), "=r"((r)[3]) : "r"(addr))

__device__ __forceinline__ void mma16816(float* d, const uint32_t* a,
                                         uint32_t b0, uint32_t b1) {
    asm volatile(
        "mma.sync.aligned.m16n8k16.row.col.f32.bf16.bf16.f32 "
        "{%0,%1,%2,%3}, {%4,%5,%6,%7}, {%8,%9}, {%0,%1,%2,%3};"
        : "+f"(d[0]), "+f"(d[1]), "+f"(d[2]), "+f"(d[3])
        : "r"(a[0]), "r"(a[1]), "r"(a[2]), "r"(a[3]), "r"(b0), "r"(b1));
}

// Fast exp on the FFMA pipe. Rel err < 3e-6 on [-87, 0].
__device__ __forceinline__ float fexp(float x) {
    x = fmaxf(x, -87.0f);
    float z  = fmaf(x, 1.44269504089f, 12582912.0f);
    float nf = z - 12582912.0f;
    float f  = fmaf(x, 1.44269504089f, -nf);
    float p  = 1.333355815e-3f;
    p = fmaf(p, f, 9.618129107e-3f);
    p = fmaf(p, f, 5.550410866e-2f);
    p = fmaf(p, f, 2.402265069e-1f);
    p = fmaf(p, f, 6.931471806e-1f);
    p = fmaf(p, f, 1.0f);
    int n = __float_as_int(z) - 0x4B400000;
    return __int_as_float(__float_as_int(p) + (n << 23));
}

// ---------------------------------------------------------------------------
// aux kernels
// ---------------------------------------------------------------------------
__global__ void split_bf16(const float* __restrict__ in,
                           __nv_bfloat16* __restrict__ oh,
                           __nv_bfloat16* __restrict__ ol, int n)
{
    int i = blockIdx.x * blockDim.x + threadIdx.x;
    if (i < n) {
        float x = in[i];
        __nv_bfloat16 h = __float2bfloat16(x);
        oh[i] = h;
        ol[i] = __float2bfloat16(x - __bfloat162float(h));
    }
}

__global__ void cvt_v16(const float* __restrict__ qkv, __half* __restrict__ out)
{
    int i = blockIdx.x * blockDim.x + threadIdx.x;
    int s = i >> 9, d = i & 511;
    out[i] = __float2half(qkv[(size_t)s * NQKV + NQ + NKVD + d]);
}

__global__ void transpose_split(const float* __restrict__ in,
                                __nv_bfloat16* __restrict__ oh,
                                __nv_bfloat16* __restrict__ ol, int R, int C)
{
    __shared__ float t[32][33];
    int c0 = blockIdx.x << 5, r0 = blockIdx.y << 5;
    int x = threadIdx.x, y = threadIdx.y;
#pragma unroll
    for (int j = y; j < 32; j += 8)
        t[j][x] = in[(size_t)(r0 + j) * C + c0 + x];
    __syncthreads();
#pragma unroll
    for (int j = y; j < 32; j += 8) {
        float v = t[x][j];
        __nv_bfloat16 h = __float2bfloat16(v);
        size_t o = (size_t)(c0 + j) * R + r0 + x;
        oh[o] = h;
        ol[o] = __float2bfloat16(v - __bfloat162float(h));
    }
}

// ---------------------------------------------------------------------------
// Raw-HMMA bf16x3 GEMM. CTA tile 128x256, 8 warps (2x4), warp tile 64x64.
// Per k16 slab: 16 LDSM.x4 feed 96 HMMA (6:1). K chunks of 32, 2-stage cp.async.
// Smem rows 80 B (64 data + 16 pad): conflict-free ldmatrix phases.
// ---------------------------------------------------------------------------
#define RPAD_B  80
#define ATILE_B (128 * RPAD_B)            // 10240
#define BTILE_B (256 * RPAD_B)            // 20480
#define STG_B   (2 * ATILE_B + 2 * BTILE_B) // 61440: Ah, Al, Bh, Bl
#define GEMM_SMEM (2 * STG_B)             // 122880

__global__ void __launch_bounds__(256, 1) gemm_mma_bf16x3(
    const __nv_bfloat16* __restrict__ Ah, const __nv_bfloat16* __restrict__ Al,
    const __nv_bfloat16* __restrict__ Bh, const __nv_bfloat16* __restrict__ Bl,
    float* __restrict__ C, int N, int K)
{
    extern __shared__ char smraw[];
    const int tid  = threadIdx.x;
    const int wid  = tid >> 5, lane = tid & 31;
    const int m0 = blockIdx.y << 7, n0 = blockIdx.x << 8;
    const int wm = wid >> 2;             // 0..1  (64-row slab)
    const int wn = wid & 3;              // 0..3  (64-col slab)

    const uint32_t sbase = smem_u32(smraw);

    float acc[4][8][4];
#pragma unroll
    for (int i = 0; i < 4; i++)
#pragma unroll
        for (int j = 0; j < 8; j++)
#pragma unroll
            for (int r = 0; r < 4; r++) acc[i][j][r] = 0.0f;

    const uint32_t lrow = lane & 15;
    const uint32_t lkof = (lane >> 4) << 4;

    const int nck = K >> 5;

    auto load_stage = [&](int ck, int s) {
        const int k0 = ck << 5;
        const uint32_t sb = sbase + s * STG_B;
        // A tiles (hi, lo): 128 rows x 4 16B-chunks each
#pragma unroll
        for (int t = 0; t < 2; t++) {
            const __nv_bfloat16* g = t ? Al : Ah;
#pragma unroll
            for (int i = 0; i < 2; i++) {
                int idx = (i << 8) + tid;          // 0..511
                int row = idx >> 2, c = idx & 3;
                cpa16(sb + t * ATILE_B + row * RPAD_B + c * 16,
                      g + (size_t)(m0 + row) * K + k0 + c * 8);
            }
        }
        // B tiles (hi, lo): 256 rows x 4 chunks each
#pragma unroll
        for (int t = 0; t < 2; t++) {
            const __nv_bfloat16* g = t ? Bl : Bh;
#pragma unroll
            for (int i = 0; i < 4; i++) {
                int idx = (i << 8) + tid;          // 0..1023
                int row = idx >> 2, c = idx & 3;
                cpa16(sb + 2 * ATILE_B + t * BTILE_B + row * RPAD_B + c * 16,
                      g + (size_t)(n0 + row) * K + k0 + c * 8);
            }
        }
        CPA_COMMIT();
    };

    load_stage(0, 0);

    for (int ck = 0; ck < nck; ck++) {
        if (ck + 1 < nck) { load_stage(ck + 1, (ck + 1) & 1); CPA_WAIT1(); }
        else             { CPA_WAIT0(); }
        __syncthreads();

        const uint32_t sb = sbase + (ck & 1) * STG_B;
        const uint32_t aHb = sb + (wm * 64 + lrow) * RPAD_B + lkof;
        const uint32_t aLb = aHb + ATILE_B;
        const uint32_t bHb = sb + 2 * ATILE_B + (wn * 64 + lrow) * RPAD_B + lkof;
        const uint32_t bLb = bHb + BTILE_B;

#pragma unroll
        for (int kk = 0; kk < 2; kk++) {
            const uint32_t ko = kk * 32;
            uint32_t bh[4][4], bl[4][4];
#pragma unroll
            for (int np = 0; np < 4; np++) {
                LDSM4(bh[np], bHb + np * 16 * RPAD_B + ko);
                LDSM4(bl[np], bLb + np * 16 * RPAD_B + ko);
            }
#pragma unroll
            for (int mt = 0; mt < 4; mt++) {
                uint32_t ah[4], al[4];
                LDSM4(ah, aHb + mt * 16 * RPAD_B + ko);
                LDSM4(al, aLb + mt * 16 * RPAD_B + ko);
#pragma unroll
                for (int nt = 0; nt < 8; nt++) {
                    const int np = nt >> 1, sl = nt & 1;
                    mma16816(acc[mt][nt], ah, bh[np][sl], bh[np][sl + 2]);
                    mma16816(acc[mt][nt], ah, bl[np][sl], bl[np][sl + 2]);
                    mma16816(acc[mt][nt], al, bh[np][sl], bh[np][sl + 2]);
                }
            }
        }
        __syncthreads();
    }

    const int erow = (lane >> 2);
    const int ecol = (lane & 3) << 1;
#pragma unroll
    for (int mt = 0; mt < 4; mt++) {
#pragma unroll
        for (int nt = 0; nt < 8; nt++) {
            const int r = m0 + wm * 64 + mt * 16 + erow;
            const int c = n0 + wn * 64 + nt * 8 + ecol;
            *(float2*)(C + (size_t)r * N + c) =
                make_float2(acc[mt][nt][0], acc[mt][nt][1]);
            *(float2*)(C + (size_t)(r + 8) * N + c) =
                make_float2(acc[mt][nt][2], acc[mt][nt][3]);
        }
    }
}

// ---------------------------------------------------------------------------
// Fused RMSNorm + RoPE, reading a column slice of fused qkv -> fp16 hi/lo
// ---------------------------------------------------------------------------
__global__ __launch_bounds__(128) void rmsnorm_rope_f16(
    const float* __restrict__ qkv, int colOff, const float* __restrict__ w,
    const float* __restrict__ cs, const float* __restrict__ sn, int heads,
    __half* __restrict__ oh, __half* __restrict__ ol)
{
    const int b = blockIdx.x;
    const int s = b / heads;
    const int h = b - s * heads;
    const int d = threadIdx.x;

    const size_t io = (size_t)s * NQKV + colOff + h * HD;
    const size_t oo = ((size_t)s * heads + h) * HD;
    float v = qkv[io + d];

    float ssq = v * v;
#pragma unroll
    for (int off = 16; off > 0; off >>= 1)
        ssq += __shfl_xor_sync(0xffffffffu, ssq, off);

    __shared__ float red[4];
    __shared__ float sh[HD];
    if ((d & 31) == 0) red[d >> 5] = ssq;
    __syncthreads();
    float tot = red[0] + red[1] + red[2] + red[3];

    float xn = v * rsqrtf(tot * (1.0f / HD) + 1e-6f) * w[d];
    sh[d] = xn;
    __syncthreads();

    float partner = (d < 64) ? -sh[d + 64] : sh[d - 64];
    float res = xn * cs[s * HD + d] + partner * sn[s * HD + d];

    __half h16 = __float2half(res);
    oh[oo + d] = h16;
    ol[oo + d] = __float2half(res - __half2float(h16));
}

// ---------------------------------------------------------------------------
// Tensor-core flash attention with double-buffered K/V prefetch.
// ---------------------------------------------------------------------------
#include <mma.h>
using namespace nvcuda;

#define QLD 136
#define SLD 132
#define PLD 72

#define OFF_QH 0
#define OFF_QL 17408
#define OFF_KV 34816          // per-buf: KH +0, KL +17408, V +34816
#define KVBUF  52224
#define OFF_S  139264
#define OFF_P  173056
#define OFF_O  182272
#define OFF_M  215040
#define OFF_L  215296
#define OFF_AL 215552
#define FLASH_SMEM 215808

__global__ void __launch_bounds__(256) flash_wmma(
    const __half* __restrict__ qh, const __half* __restrict__ ql,
    const __half* __restrict__ kh, const __half* __restrict__ kl,
    const __half* __restrict__ vv,
    __nv_bfloat16* __restrict__ oh, __nv_bfloat16* __restrict__ ol)
{
    extern __shared__ char smc[];
    __half* sQh = (__half*)(smc + OFF_QH);
    __half* sQl = (__half*)(smc + OFF_QL);
    float*  sS  = (float*)(smc + OFF_S);
    __half* sP  = (__half*)(smc + OFF_P);
    float*  sO  = (float*)(smc + OFF_O);
    float*  sM  = (float*)(smc + OFF_M);
    float*  sL  = (float*)(smc + OFF_L);
    float*  sA  = (float*)(smc + OFF_AL);

    const int h     = blockIdx.x;
    const int ptile = (int)gridDim.y - 1 - blockIdx.y;
    const int m0    = ptile << 6;
    const int kvh   = h >> 3;
    const int tid   = threadIdx.x;
    const int wid   = tid >> 5;
    const int rs    = wid >> 1;
    const int ch    = wid & 1;
    const float scale = 0.08838834764831845f;

    auto load_kv = [&](int kb, int buf) {
        const int k0g = kb << 6;
        const uint32_t base = smem_u32(smc) + OFF_KV + buf * KVBUF;
#pragma unroll
        for (int i = 0; i < 4; i++) {
            int idx = tid + (i << 8);
            int r = idx >> 4, c = idx & 15;
            size_t so = (size_t)(k0g + r) * NKVD + kvh * HD + (c << 3);
            uint32_t off = r * (QLD * 2) + (c << 4);
            cpa16(base + off,         kh + so);
            cpa16(base + 17408 + off, kl + so);
            cpa16(base + 34816 + off, vv + so);
        }
        CPA_COMMIT();
    };

    {
        uint32_t dqh = smem_u32(sQh), dql = smem_u32(sQl);
#pragma unroll
        for (int i = 0; i < 4; i++) {
            int idx = tid + (i << 8);
            int r = idx >> 4, c = idx & 15;
            size_t so = (size_t)(m0 + r) * NQ + h * HD + (c << 3);
            uint32_t off = r * (QLD * 2) + (c << 4);
            cpa16(dqh + off, qh + so);
            cpa16(dql + off, ql + so);
        }
        CPA_COMMIT();
    }
    load_kv(0, 0);

    for (int i = tid; i < 64 * 128 / 4; i += 256)
        ((float4*)sO)[i] = make_float4(0.f, 0.f, 0.f, 0.f);
    if (tid < 64) { sM[tid] = -1e30f; sL[tid] = 0.f; }

    for (int kb = 0; kb <= ptile; kb++) {
        const int k0g = kb << 6;
        const int buf = kb & 1;
        __half* sKh = (__half*)(smc + OFF_KV + buf * KVBUF);
        __half* sKl = (__half*)(smc + OFF_KV + buf * KVBUF + 17408);
        __half* sV  = (__half*)(smc + OFF_KV + buf * KVBUF + 34816);

        if (kb < ptile) { load_kv(kb + 1, buf ^ 1); CPA_WAIT1(); }
        else            { CPA_WAIT0(); }
        __syncthreads();

        {
            wmma::fragment<wmma::accumulator, 16, 16, 16, float> accS[2];
            wmma::fill_fragment(accS[0], 0.0f);
            wmma::fill_fragment(accS[1], 0.0f);
#pragma unroll
            for (int k0 = 0; k0 < 128; k0 += 16) {
                wmma::fragment<wmma::matrix_a, 16, 16, 16, __half, wmma::row_major> ah, al;
                wmma::load_matrix_sync(ah, sQh + rs * 16 * QLD + k0, QLD);
                wmma::load_matrix_sync(al, sQl + rs * 16 * QLD + k0, QLD);
#pragma unroll
                for (int j = 0; j < 2; j++) {
                    wmma::fragment<wmma::matrix_b, 16, 16, 16, __half, wmma::col_major> bh, bl;
                    int kcol = ch * 32 + j * 16;
                    wmma::load_matrix_sync(bh, sKh + kcol * QLD + k0, QLD);
                    wmma::load_matrix_sync(bl, sKl + kcol * QLD + k0, QLD);
                    wmma::mma_sync(accS[j], ah, bh, accS[j]);
                    wmma::mma_sync(accS[j], ah, bl, accS[j]);
                    wmma::mma_sync(accS[j], al, bh, accS[j]);
                }
            }
#pragma unroll
            for (int j = 0; j < 2; j++)
                wmma::store_matrix_sync(sS + rs * 16 * SLD + ch * 32 + j * 16,
                                        accS[j], SLD, wmma::mem_row_major);
        }
        __syncthreads();

        {
            const int r  = tid >> 2;
            const int q4 = tid & 3;
            float* srow = sS + r * SLD + q4 * 16;
            const int qglob = m0 + r;
            const int kbase = k0g + q4 * 16;

            float vals[16];
            float mx = -1e30f;
#pragma unroll
            for (int j = 0; j < 16; j++) {
                float s = srow[j];
                s = (kbase + j <= qglob) ? s * scale : -1e30f;
                vals[j] = s;
                mx = fmaxf(mx, s);
            }
            mx = fmaxf(mx, __shfl_xor_sync(0xffffffffu, mx, 1));
            mx = fmaxf(mx, __shfl_xor_sync(0xffffffffu, mx, 2));

            float mold = sM[r];
            float mnew = fmaxf(mold, mx);
            float alpha = fexp(mold - mnew);

            __half* prow = sP + r * PLD + q4 * 16;
            float lsum = 0.f;
#pragma unroll
            for (int j = 0; j < 16; j++) {
                float p = fexp(vals[j] - mnew);
                prow[j] = __float2half(p);
                lsum += p;
            }
            lsum += __shfl_xor_sync(0xffffffffu, lsum, 1);
            lsum += __shfl_xor_sync(0xffffffffu, lsum, 2);

            if (q4 == 0) {
                sM[r] = mnew;
                sL[r] = sL[r] * alpha + lsum;
                sA[r] = alpha;
            }
        }
        __syncthreads();

        {
            wmma::fragment<wmma::accumulator, 16, 16, 16, float> accO[4];
#pragma unroll
            for (int j = 0; j < 4; j++) wmma::fill_fragment(accO[j], 0.0f);
#pragma unroll
            for (int k0 = 0; k0 < 64; k0 += 16) {
                wmma::fragment<wmma::matrix_a, 16, 16, 16, __half, wmma::row_major> a;
                wmma::load_matrix_sync(a, sP + rs * 16 * PLD + k0, PLD);
#pragma unroll
                for (int j = 0; j < 4; j++) {
                    wmma::fragment<wmma::matrix_b, 16, 16, 16, __half, wmma::row_major> b;
                    wmma::load_matrix_sync(b, sV + k0 * QLD + ch * 64 + j * 16, QLD);
                    wmma::mma_sync(accO[j], a, b, accO[j]);
                }
            }
#pragma unroll
            for (int j = 0; j < 4; j++)
                wmma::store_matrix_sync(sS + rs * 16 * SLD + ch * 64 + j * 16,
                                        accO[j], SLD, wmma::mem_row_major);
        }
        __syncthreads();

        {
            const int r  = tid >> 2;
            const int c0 = (tid & 3) << 5;
            const float a = sA[r];
            float4* op = (float4*)(sO + r * 128 + c0);
            const float4* pv = (const float4*)(sS + r * SLD + c0);
#pragma unroll
            for (int j = 0; j < 8; j++) {
                float4 o = op[j], p = pv[j];
                o.x = o.x * a + p.x;
                o.y = o.y * a + p.y;
                o.z = o.z * a + p.z;
                o.w = o.w * a + p.w;
                op[j] = o;
            }
        }
        __syncthreads();
    }

    {
        const int r  = tid >> 2;
        const int c0 = (tid & 3) << 5;
        const float inv = 1.0f / sL[r];
        const size_t base = (size_t)(m0 + r) * NQ + h * HD + c0;
#pragma unroll
        for (int j = 0; j < 32; j++) {
            float o = sO[r * 128 + c0 + j] * inv;
            __nv_bfloat16 hi = __float2bfloat16(o);
            oh[base + j] = hi;
            ol[base + j] = __float2bfloat16(o - __bfloat162float(hi));
        }
    }
}

// ---------------------------------------------------------------------------
extern "C" void kernel_launch(void* const* d_in, const int* in_sizes, int n_in,
                              void* d_out, int out_size)
{
    (void)in_sizes; (void)n_in; (void)out_size;
    const float* x  = (const float*)d_in[0];
    const float* wq = (const float*)d_in[1];
    const float* wk = (const float*)d_in[2];
    const float* wv = (const float*)d_in[3];
    const float* wo = (const float*)d_in[4];
    const float* qn = (const float*)d_in[5];
    const float* kn = (const float*)d_in[6];
    const float* cs = (const float*)d_in[7];
    const float* sn = (const float*)d_in[8];
    float* out = (float*)d_out;

    float* qkv;
    cudaGetSymbolAddress((void**)&qkv, g_qkv);

    __nv_bfloat16 *xh, *xl, *wTh, *wTl, *woTh, *woTl, *ath, *atl;
    cudaGetSymbolAddress((void**)&xh,   g_xh);
    cudaGetSymbolAddress((void**)&xl,   g_xl);
    cudaGetSymbolAddress((void**)&wTh,  g_wqkvTh);
    cudaGetSymbolAddress((void**)&wTl,  g_wqkvTl);
    cudaGetSymbolAddress((void**)&woTh, g_woTh);
    cudaGetSymbolAddress((void**)&woTl, g_woTl);
    cudaGetSymbolAddress((void**)&ath,  g_ath);
    cudaGetSymbolAddress((void**)&atl,  g_atl);

    __half *q16h, *q16l, *k16h, *k16l, *v16;
    cudaGetSymbolAddress((void**)&q16h, g_q16h);
    cudaGetSymbolAddress((void**)&q16l, g_q16l);
    cudaGetSymbolAddress((void**)&k16h, g_k16h);
    cudaGetSymbolAddress((void**)&k16l, g_k16l);
    cudaGetSymbolAddress((void**)&v16,  g_v16);

    cudaFuncSetAttribute(gemm_mma_bf16x3,
                         cudaFuncAttributeMaxDynamicSharedMemorySize, GEMM_SMEM);
    cudaFuncSetAttribute(flash_wmma,
                         cudaFuncAttributeMaxDynamicSharedMemorySize, FLASH_SMEM);

    split_bf16<<<(S_LEN * HID + 255) / 256, 256>>>(x, xh, xl, S_LEN * HID);
    transpose_split<<<dim3(NQ / 32,   HID / 32), dim3(32, 8)>>>(
        wq, wTh, wTl, HID, NQ);
    transpose_split<<<dim3(NKVD / 32, HID / 32), dim3(32, 8)>>>(
        wk, wTh + (size_t)NQ * HID, wTl + (size_t)NQ * HID, HID, NKVD);
    transpose_split<<<dim3(NKVD / 32, HID / 32), dim3(32, 8)>>>(
        wv, wTh + (size_t)(NQ + NKVD) * HID, wTl + (size_t)(NQ + NKVD) * HID, HID, NKVD);
    transpose_split<<<dim3(HID / 32,  NQ / 32),  dim3(32, 8)>>>(wo, woTh, woTl, NQ, HID);

    // Fused QKV projection: grid (5120/256, 2048/128)
    gemm_mma_bf16x3<<<dim3(NQKV / 256, S_LEN / 128), 256, GEMM_SMEM>>>(
        xh, xl, wTh, wTl, qkv, NQKV, HID);

    // RMSNorm + RoPE -> fp16 hi/lo; V -> fp16
    rmsnorm_rope_f16<<<S_LEN * NH,  128>>>(qkv, 0,  qn, cs, sn, NH,  q16h, q16l);
    rmsnorm_rope_f16<<<S_LEN * NKV, 128>>>(qkv, NQ, kn, cs, sn, NKV, k16h, k16l);
    cvt_v16<<<(S_LEN * NKVD) / 256, 256>>>(qkv, v16);

    // Flash attention
    flash_wmma<<<dim3(NH, S_LEN / 64), 256, FLASH_SMEM>>>(
        q16h, q16l, k16h, k16l, v16, ath, atl);

    // Output projection: grid (2048/256, 2048/128)
    gemm_mma_bf16x3<<<dim3(HID / 256, S_LEN / 128), 256, GEMM_SMEM>>>(
        ath, atl, woTh, woTl, out, HID, NQ);
}

// round 8
// speedup vs baseline: 1.3129x; 1.3129x over previous
#include <cuda_runtime.h>
#include <cuda_bf16.h>
#include <cuda_fp16.h>
#include <cstdint>
#include <math.h>

#define S_LEN 2048
#define HID   2048
#define NH    32
#define NKV   4
#define HD    128
#define NQ    (NH * HD)    // 4096
#define NKVD  (NKV * HD)   // 512
#define NQKV  (NQ + 2 * NKVD)  // 5120

// ---------------------------------------------------------------------------
// Scratch (device globals — no allocation allowed)
// ---------------------------------------------------------------------------
__device__ float g_qkv[S_LEN * NQKV];

__device__ __half g_xh[S_LEN * HID];
__device__ __half g_xl[S_LEN * HID];
__device__ __half g_wqkvT[NQKV * HID];   // fp16 weights, [N][K]
__device__ __half g_woT[HID * NQ];
__device__ __half g_ath[S_LEN * NQ];
__device__ __half g_atl[S_LEN * NQ];

__device__ __half g_q16h[S_LEN * NQ];
__device__ __half g_q16l[S_LEN * NQ];
__device__ __half g_k16h[S_LEN * NKVD];
__device__ __half g_v16[S_LEN * NKVD];

// ---------------------------------------------------------------------------
// helpers
// ---------------------------------------------------------------------------
__device__ __forceinline__ uint32_t smem_u32(const void* p) {
    uint32_t a;
    asm("{ .reg .u64 t; cvta.to.shared.u64 t, %1; cvt.u32.u64 %0, t; }"
        : "=r"(a) : "l"(p));
    return a;
}

__device__ __forceinline__ void cpa16(uint32_t dst, const void* src) {
    asm volatile(
        "{\n\t.reg .u64 g;\n\tcvta.to.global.u64 g, %1;\n\t"
        "cp.async.cg.shared.global [%0], [g], 16;\n\t}"
        :: "r"(dst), "l"(src) : "memory");
}
#define CPA_COMMIT() asm volatile("cp.async.commit_group;" ::: "memory")
#define CPA_WAIT1()  asm volatile("cp.async.wait_group 1;" ::: "memory")
#define CPA_WAIT0()  asm volatile("cp.async.wait_group 0;" ::: "memory")

#define LDSM4(r, addr) \
    asm volatile("ldmatrix.sync.aligned.m8n8.x4.shared.b16 {%0,%1,%2,%3}, [%4];" \
        : "=r"((r)[0]), "=r"((r)[1]), "=r"((r)[2]), "=r"((r)[3]) : "r"(addr))

__device__ __forceinline__ void mma16816f(float* d, const uint32_t* a,
                                          uint32_t b0, uint32_t b1) {
    asm volatile(
        "mma.sync.aligned.m16n8k16.row.col.f32.f16.f16.f32 "
        "{%0,%1,%2,%3}, {%4,%5,%6,%7}, {%8,%9}, {%0,%1,%2,%3};"
        : "+f"(d[0]), "+f"(d[1]), "+f"(d[2]), "+f"(d[3])
        : "r"(a[0]), "r"(a[1]), "r"(a[2]), "r"(a[3]), "r"(b0), "r"(b1));
}

// Fast exp on the FFMA pipe. Rel err < 3e-6 on [-87, 0].
__device__ __forceinline__ float fexp(float x) {
    x = fmaxf(x, -87.0f);
    float z  = fmaf(x, 1.44269504089f, 12582912.0f);
    float nf = z - 12582912.0f;
    float f  = fmaf(x, 1.44269504089f, -nf);
    float p  = 1.333355815e-3f;
    p = fmaf(p, f, 9.618129107e-3f);
    p = fmaf(p, f, 5.550410866e-2f);
    p = fmaf(p, f, 2.402265069e-1f);
    p = fmaf(p, f, 6.931471806e-1f);
    p = fmaf(p, f, 1.0f);
    int n = __float_as_int(z) - 0x4B400000;
    return __int_as_float(__float_as_int(p) + (n << 23));
}

// ---------------------------------------------------------------------------
// aux kernels
// ---------------------------------------------------------------------------
__global__ void split_f16(const float* __restrict__ in,
                          __half* __restrict__ oh,
                          __half* __restrict__ ol, int n)
{
    int i = blockIdx.x * blockDim.x + threadIdx.x;
    if (i < n) {
        float x = in[i];
        __half h = __float2half(x);
        oh[i] = h;
        ol[i] = __float2half(x - __half2float(h));
    }
}

__global__ void cvt_v16(const float* __restrict__ qkv, __half* __restrict__ out)
{
    int i = blockIdx.x * blockDim.x + threadIdx.x;
    int s = i >> 9, d = i & 511;
    out[i] = __float2half(qkv[(size_t)s * NQKV + NQ + NKVD + d]);
}

// Transpose [R][C] fp32 -> [C][R] fp16
__global__ void transpose_f16(const float* __restrict__ in,
                              __half* __restrict__ o, int R, int C)
{
    __shared__ float t[32][33];
    int c0 = blockIdx.x << 5, r0 = blockIdx.y << 5;
    int x = threadIdx.x, y = threadIdx.y;
#pragma unroll
    for (int j = y; j < 32; j += 8)
        t[j][x] = in[(size_t)(r0 + j) * C + c0 + x];
    __syncthreads();
#pragma unroll
    for (int j = y; j < 32; j += 8)
        o[(size_t)(c0 + j) * R + r0 + x] = __float2half(t[x][j]);
}

// ---------------------------------------------------------------------------
// Raw-HMMA fp16x2 GEMM: C[m][n] = sum_k (Ah+Al)[m][k] * B[n][k]
// A hi/lo fp16 (22-bit activations), B single fp16 (weights).
// CTA 128x128, 8 warps, warp tile 64x32. K chunks of 32, 2-stage cp.async.
// Per k16 slab: 10 LDSM.x4 feed 32 HMMA. 2 CTAs/SM (smem 61 KB).
// ---------------------------------------------------------------------------
#define RPAD_B 80
#define TILE_B (128 * RPAD_B)            // 10240
#define STG_B  (3 * TILE_B)              // 30720: Ah, Al, B
#define GEMM_SMEM (2 * STG_B)            // 61440

__global__ void __launch_bounds__(256, 2) gemm_mma_f16x2(
    const __half* __restrict__ Ah, const __half* __restrict__ Al,
    const __half* __restrict__ B,
    float* __restrict__ C, int N, int K)
{
    extern __shared__ char smraw[];
    const int tid  = threadIdx.x;
    const int wid  = tid >> 5, lane = tid & 31;
    const int m0 = blockIdx.y << 7, n0 = blockIdx.x << 7;
    const int wm = wid >> 2;             // 0..1  (64-row slab)
    const int wn = wid & 3;              // 0..3  (32-col slab)

    const uint32_t sbase = smem_u32(smraw);

    float acc[4][4][4];
#pragma unroll
    for (int i = 0; i < 4; i++)
#pragma unroll
        for (int j = 0; j < 4; j++)
#pragma unroll
            for (int r = 0; r < 4; r++) acc[i][j][r] = 0.0f;

    const uint32_t lrow = lane & 15;
    const uint32_t lkof = (lane >> 4) << 4;

    const __half* gb[3] = {Ah, Al, B};
    const int gr0[3] = {m0, m0, n0};
    const int nck = K >> 5;

    auto load_stage = [&](int ck, int s) {
        const int k0 = ck << 5;
        const uint32_t sb = sbase + s * STG_B;
#pragma unroll
        for (int t = 0; t < 3; t++) {
#pragma unroll
            for (int i = 0; i < 2; i++) {
                int idx = (i << 8) + tid;          // 0..511
                int row = idx >> 2, c = idx & 3;
                cpa16(sb + t * TILE_B + row * RPAD_B + c * 16,
                      gb[t] + (size_t)(gr0[t] + row) * K + k0 + c * 8);
            }
        }
        CPA_COMMIT();
    };

    load_stage(0, 0);

    for (int ck = 0; ck < nck; ck++) {
        if (ck + 1 < nck) { load_stage(ck + 1, (ck + 1) & 1); CPA_WAIT1(); }
        else             { CPA_WAIT0(); }
        __syncthreads();

        const uint32_t sb = sbase + (ck & 1) * STG_B;
        const uint32_t aHb = sb + (wm * 64 + lrow) * RPAD_B + lkof;
        const uint32_t aLb = aHb + TILE_B;
        const uint32_t bb  = sb + 2 * TILE_B + (wn * 32 + lrow) * RPAD_B + lkof;

#pragma unroll
        for (int kk = 0; kk < 2; kk++) {
            const uint32_t ko = kk * 32;
            uint32_t bh[2][4];
#pragma unroll
            for (int np = 0; np < 2; np++)
                LDSM4(bh[np], bb + np * 16 * RPAD_B + ko);
#pragma unroll
            for (int mt = 0; mt < 4; mt++) {
                uint32_t ah[4], al[4];
                LDSM4(ah, aHb + mt * 16 * RPAD_B + ko);
                LDSM4(al, aLb + mt * 16 * RPAD_B + ko);
#pragma unroll
                for (int nt = 0; nt < 4; nt++) {
                    const int np = nt >> 1, sl = nt & 1;
                    mma16816f(acc[mt][nt], ah, bh[np][sl], bh[np][sl + 2]);
                    mma16816f(acc[mt][nt], al, bh[np][sl], bh[np][sl + 2]);
                }
            }
        }
        __syncthreads();
    }

    const int erow = (lane >> 2);
    const int ecol = (lane & 3) << 1;
#pragma unroll
    for (int mt = 0; mt < 4; mt++) {
#pragma unroll
        for (int nt = 0; nt < 4; nt++) {
            const int r = m0 + wm * 64 + mt * 16 + erow;
            const int c = n0 + wn * 32 + nt * 8 + ecol;
            *(float2*)(C + (size_t)r * N + c) =
                make_float2(acc[mt][nt][0], acc[mt][nt][1]);
            *(float2*)(C + (size_t)(r + 8) * N + c) =
                make_float2(acc[mt][nt][2], acc[mt][nt][3]);
        }
    }
}

// ---------------------------------------------------------------------------
// Fused RMSNorm + RoPE, reading a column slice of fused qkv -> fp16 hi/lo
// ---------------------------------------------------------------------------
__global__ __launch_bounds__(128) void rmsnorm_rope_f16(
    const float* __restrict__ qkv, int colOff, const float* __restrict__ w,
    const float* __restrict__ cs, const float* __restrict__ sn, int heads,
    __half* __restrict__ oh, __half* __restrict__ ol)
{
    const int b = blockIdx.x;
    const int s = b / heads;
    const int h = b - s * heads;
    const int d = threadIdx.x;

    const size_t io = (size_t)s * NQKV + colOff + h * HD;
    const size_t oo = ((size_t)s * heads + h) * HD;
    float v = qkv[io + d];

    float ssq = v * v;
#pragma unroll
    for (int off = 16; off > 0; off >>= 1)
        ssq += __shfl_xor_sync(0xffffffffu, ssq, off);

    __shared__ float red[4];
    __shared__ float sh[HD];
    if ((d & 31) == 0) red[d >> 5] = ssq;
    __syncthreads();
    float tot = red[0] + red[1] + red[2] + red[3];

    float xn = v * rsqrtf(tot * (1.0f / HD) + 1e-6f) * w[d];
    sh[d] = xn;
    __syncthreads();

    float partner = (d < 64) ? -sh[d + 64] : sh[d - 64];
    float res = xn * cs[s * HD + d] + partner * sn[s * HD + d];

    __half h16 = __float2half(res);
    oh[oo + d] = h16;
    if (ol) ol[oo + d] = __float2half(res - __half2float(h16));
}

// ---------------------------------------------------------------------------
// Tensor-core flash attention, double-buffered K/V prefetch.
// QK: Q fp16 hi/lo x K fp16 (2 MMAs). P,V fp16. O fp32 smem.
// Epilogue writes fp16 hi/lo for the output projection.
// ---------------------------------------------------------------------------
#include <mma.h>
using namespace nvcuda;

#define QLD 136
#define SLD 132
#define PLD 72

#define OFF_QH 0
#define OFF_QL 17408
#define OFF_KV 34816          // per-buf: KH +0, V +17408
#define KVBUF  34816
#define OFF_S  104448
#define OFF_P  138240
#define OFF_O  147456
#define OFF_M  180224
#define OFF_L  180480
#define OFF_AL 180736
#define FLASH_SMEM 180992

__global__ void __launch_bounds__(256) flash_wmma(
    const __half* __restrict__ qh, const __half* __restrict__ ql,
    const __half* __restrict__ kh, const __half* __restrict__ vv,
    __half* __restrict__ oh, __half* __restrict__ ol)
{
    extern __shared__ char smc[];
    __half* sQh = (__half*)(smc + OFF_QH);
    __half* sQl = (__half*)(smc + OFF_QL);
    float*  sS  = (float*)(smc + OFF_S);
    __half* sP  = (__half*)(smc + OFF_P);
    float*  sO  = (float*)(smc + OFF_O);
    float*  sM  = (float*)(smc + OFF_M);
    float*  sL  = (float*)(smc + OFF_L);
    float*  sA  = (float*)(smc + OFF_AL);

    const int h     = blockIdx.x;
    const int ptile = (int)gridDim.y - 1 - blockIdx.y;
    const int m0    = ptile << 6;
    const int kvh   = h >> 3;
    const int tid   = threadIdx.x;
    const int wid   = tid >> 5;
    const int rs    = wid >> 1;
    const int ch    = wid & 1;
    const float scale = 0.08838834764831845f;

    auto load_kv = [&](int kb, int buf) {
        const int k0g = kb << 6;
        const uint32_t base = smem_u32(smc) + OFF_KV + buf * KVBUF;
#pragma unroll
        for (int i = 0; i < 4; i++) {
            int idx = tid + (i << 8);
            int r = idx >> 4, c = idx & 15;
            size_t so = (size_t)(k0g + r) * NKVD + kvh * HD + (c << 3);
            uint32_t off = r * (QLD * 2) + (c << 4);
            cpa16(base + off,         kh + so);
            cpa16(base + 17408 + off, vv + so);
        }
        CPA_COMMIT();
    };

    {
        uint32_t dqh = smem_u32(sQh), dql = smem_u32(sQl);
#pragma unroll
        for (int i = 0; i < 4; i++) {
            int idx = tid + (i << 8);
            int r = idx >> 4, c = idx & 15;
            size_t so = (size_t)(m0 + r) * NQ + h * HD + (c << 3);
            uint32_t off = r * (QLD * 2) + (c << 4);
            cpa16(dqh + off, qh + so);
            cpa16(dql + off, ql + so);
        }
        CPA_COMMIT();
    }
    load_kv(0, 0);

    for (int i = tid; i < 64 * 128 / 4; i += 256)
        ((float4*)sO)[i] = make_float4(0.f, 0.f, 0.f, 0.f);
    if (tid < 64) { sM[tid] = -1e30f; sL[tid] = 0.f; }

    for (int kb = 0; kb <= ptile; kb++) {
        const int k0g = kb << 6;
        const int buf = kb & 1;
        __half* sKh = (__half*)(smc + OFF_KV + buf * KVBUF);
        __half* sV  = (__half*)(smc + OFF_KV + buf * KVBUF + 17408);

        if (kb < ptile) { load_kv(kb + 1, buf ^ 1); CPA_WAIT1(); }
        else            { CPA_WAIT0(); }
        __syncthreads();

        // --- QK^T: (Qh + Ql) x Kh ---
        {
            wmma::fragment<wmma::accumulator, 16, 16, 16, float> accS[2];
            wmma::fill_fragment(accS[0], 0.0f);
            wmma::fill_fragment(accS[1], 0.0f);
#pragma unroll
            for (int k0 = 0; k0 < 128; k0 += 16) {
                wmma::fragment<wmma::matrix_a, 16, 16, 16, __half, wmma::row_major> ah, al;
                wmma::load_matrix_sync(ah, sQh + rs * 16 * QLD + k0, QLD);
                wmma::load_matrix_sync(al, sQl + rs * 16 * QLD + k0, QLD);
#pragma unroll
                for (int j = 0; j < 2; j++) {
                    wmma::fragment<wmma::matrix_b, 16, 16, 16, __half, wmma::col_major> bh;
                    int kcol = ch * 32 + j * 16;
                    wmma::load_matrix_sync(bh, sKh + kcol * QLD + k0, QLD);
                    wmma::mma_sync(accS[j], ah, bh, accS[j]);
                    wmma::mma_sync(accS[j], al, bh, accS[j]);
                }
            }
#pragma unroll
            for (int j = 0; j < 2; j++)
                wmma::store_matrix_sync(sS + rs * 16 * SLD + ch * 32 + j * 16,
                                        accS[j], SLD, wmma::mem_row_major);
        }
        __syncthreads();

        // --- online softmax ---
        {
            const int r  = tid >> 2;
            const int q4 = tid & 3;
            float* srow = sS + r * SLD + q4 * 16;
            const int qglob = m0 + r;
            const int kbase = k0g + q4 * 16;

            float vals[16];
            float mx = -1e30f;
#pragma unroll
            for (int j = 0; j < 16; j++) {
                float s = srow[j];
                s = (kbase + j <= qglob) ? s * scale : -1e30f;
                vals[j] = s;
                mx = fmaxf(mx, s);
            }
            mx = fmaxf(mx, __shfl_xor_sync(0xffffffffu, mx, 1));
            mx = fmaxf(mx, __shfl_xor_sync(0xffffffffu, mx, 2));

            float mold = sM[r];
            float mnew = fmaxf(mold, mx);
            float alpha = fexp(mold - mnew);

            __half* prow = sP + r * PLD + q4 * 16;
            float lsum = 0.f;
#pragma unroll
            for (int j = 0; j < 16; j++) {
                float p = fexp(vals[j] - mnew);
                prow[j] = __float2half(p);
                lsum += p;
            }
            lsum += __shfl_xor_sync(0xffffffffu, lsum, 1);
            lsum += __shfl_xor_sync(0xffffffffu, lsum, 2);

            if (q4 == 0) {
                sM[r] = mnew;
                sL[r] = sL[r] * alpha + lsum;
                sA[r] = alpha;
            }
        }
        __syncthreads();

        // --- P @ V ---
        {
            wmma::fragment<wmma::accumulator, 16, 16, 16, float> accO[4];
#pragma unroll
            for (int j = 0; j < 4; j++) wmma::fill_fragment(accO[j], 0.0f);
#pragma unroll
            for (int k0 = 0; k0 < 64; k0 += 16) {
                wmma::fragment<wmma::matrix_a, 16, 16, 16, __half, wmma::row_major> a;
                wmma::load_matrix_sync(a, sP + rs * 16 * PLD + k0, PLD);
#pragma unroll
                for (int j = 0; j < 4; j++) {
                    wmma::fragment<wmma::matrix_b, 16, 16, 16, __half, wmma::row_major> b;
                    wmma::load_matrix_sync(b, sV + k0 * QLD + ch * 64 + j * 16, QLD);
                    wmma::mma_sync(accO[j], a, b, accO[j]);
                }
            }
#pragma unroll
            for (int j = 0; j < 4; j++)
                wmma::store_matrix_sync(sS + rs * 16 * SLD + ch * 64 + j * 16,
                                        accO[j], SLD, wmma::mem_row_major);
        }
        __syncthreads();

        // --- O = O*alpha + PV ---
        {
            const int r  = tid >> 2;
            const int c0 = (tid & 3) << 5;
            const float a = sA[r];
            float4* op = (float4*)(sO + r * 128 + c0);
            const float4* pv = (const float4*)(sS + r * SLD + c0);
#pragma unroll
            for (int j = 0; j < 8; j++) {
                float4 o = op[j], p = pv[j];
                o.x = o.x * a + p.x;
                o.y = o.y * a + p.y;
                o.z = o.z * a + p.z;
                o.w = o.w * a + p.w;
                op[j] = o;
            }
        }
        __syncthreads();
    }

    // Epilogue: normalize, write fp16 hi/lo
    {
        const int r  = tid >> 2;
        const int c0 = (tid & 3) << 5;
        const float inv = 1.0f / sL[r];
        const size_t base = (size_t)(m0 + r) * NQ + h * HD + c0;
#pragma unroll
        for (int j = 0; j < 32; j++) {
            float o = sO[r * 128 + c0 + j] * inv;
            __half hi = __float2half(o);
            oh[base + j] = hi;
            ol[base + j] = __float2half(o - __half2float(hi));
        }
    }
}

// ---------------------------------------------------------------------------
extern "C" void kernel_launch(void* const* d_in, const int* in_sizes, int n_in,
                              void* d_out, int out_size)
{
    (void)in_sizes; (void)n_in; (void)out_size;
    const float* x  = (const float*)d_in[0];
    const float* wq = (const float*)d_in[1];
    const float* wk = (const float*)d_in[2];
    const float* wv = (const float*)d_in[3];
    const float* wo = (const float*)d_in[4];
    const float* qn = (const float*)d_in[5];
    const float* kn = (const float*)d_in[6];
    const float* cs = (const float*)d_in[7];
    const float* sn = (const float*)d_in[8];
    float* out = (float*)d_out;

    float* qkv;
    cudaGetSymbolAddress((void**)&qkv, g_qkv);

    __half *xh, *xl, *wT, *woT, *ath, *atl;
    cudaGetSymbolAddress((void**)&xh,  g_xh);
    cudaGetSymbolAddress((void**)&xl,  g_xl);
    cudaGetSymbolAddress((void**)&wT,  g_wqkvT);
    cudaGetSymbolAddress((void**)&woT, g_woT);
    cudaGetSymbolAddress((void**)&ath, g_ath);
    cudaGetSymbolAddress((void**)&atl, g_atl);

    __half *q16h, *q16l, *k16h, *v16;
    cudaGetSymbolAddress((void**)&q16h, g_q16h);
    cudaGetSymbolAddress((void**)&q16l, g_q16l);
    cudaGetSymbolAddress((void**)&k16h, g_k16h);
    cudaGetSymbolAddress((void**)&v16,  g_v16);

    cudaFuncSetAttribute(gemm_mma_f16x2,
                         cudaFuncAttributeMaxDynamicSharedMemorySize, GEMM_SMEM);
    cudaFuncSetAttribute(flash_wmma,
                         cudaFuncAttributeMaxDynamicSharedMemorySize, FLASH_SMEM);

    // Split activations to fp16 hi/lo; transpose weights to fp16 [N][K]
    split_f16<<<(S_LEN * HID + 255) / 256, 256>>>(x, xh, xl, S_LEN * HID);
    transpose_f16<<<dim3(NQ / 32,   HID / 32), dim3(32, 8)>>>(wq, wT, HID, NQ);
    transpose_f16<<<dim3(NKVD / 32, HID / 32), dim3(32, 8)>>>(
        wk, wT + (size_t)NQ * HID, HID, NKVD);
    transpose_f16<<<dim3(NKVD / 32, HID / 32), dim3(32, 8)>>>(
        wv, wT + (size_t)(NQ + NKVD) * HID, HID, NKVD);
    transpose_f16<<<dim3(HID / 32,  NQ / 32),  dim3(32, 8)>>>(wo, woT, NQ, HID);

    // Fused QKV projection (fp16x2 HMMA): grid (5120/128, 2048/128)
    gemm_mma_f16x2<<<dim3(NQKV / 128, S_LEN / 128), 256, GEMM_SMEM>>>(
        xh, xl, wT, qkv, NQKV, HID);

    // RMSNorm + RoPE -> fp16 hi/lo (K: hi only); V -> fp16
    rmsnorm_rope_f16<<<S_LEN * NH,  128>>>(qkv, 0,  qn, cs, sn, NH,  q16h, q16l);
    rmsnorm_rope_f16<<<S_LEN * NKV, 128>>>(qkv, NQ, kn, cs, sn, NKV, k16h, (half*)0);
    cvt_v16<<<(S_LEN * NKVD) / 256, 256>>>(qkv, v16);

    // Flash attention -> fp16 hi/lo
    flash_wmma<<<dim3(NH, S_LEN / 64), 256, FLASH_SMEM>>>(
        q16h, q16l, k16h, v16, ath, atl);

    // Output projection
    gemm_mma_f16x2<<<dim3(HID / 128, S_LEN / 128), 256, GEMM_SMEM>>>(
        ath, atl, woT, out, HID, NQ);
}